// round 5
// baseline (speedup 1.0000x reference)
#include <cuda_runtime.h>
#include <cuda_bf16.h>

#define BB 64
#define NN 2048
#define DD 256
#define EPS 1e-05f

#define CHUNKS 16
#define ROWS_PER_CHUNK (NN / CHUNKS)  // 128

// Per-(batch, chunk) partial (sum, sumsq). Each stats block owns exactly one
// slot and writes it unconditionally every launch -> no zeroing kernel, no
// atomics, deterministic.
__device__ float2 g_partial[BB * CHUNKS];

// Pass 1: per-batch-chunk sum and sum-of-squares over valid rows only.
// grid = (CHUNKS, B), block = 256 threads.
__global__ __launch_bounds__(256) void stats_kernel(const float* __restrict__ x,
                                                    const int* __restrict__ lengths) {
    const int b = blockIdx.y;
    const int len = lengths[b];
    const int row0 = blockIdx.x * ROWS_PER_CHUNK;
    const int row1 = min(row0 + ROWS_PER_CHUNK, len);

    float s = 0.0f, ss = 0.0f;
    if (row1 > row0) {
        const float4* __restrict__ p =
            reinterpret_cast<const float4*>(x + (size_t)b * NN * DD) + (size_t)row0 * (DD / 4);
        const int nvec = (row1 - row0) * (DD / 4);
        for (int i = threadIdx.x; i < nvec; i += 256) {
            float4 v = p[i];
            s  += (v.x + v.y) + (v.z + v.w);
            ss += v.x * v.x + v.y * v.y + v.z * v.z + v.w * v.w;
        }
    }

    // warp reduce
    #pragma unroll
    for (int off = 16; off > 0; off >>= 1) {
        s  += __shfl_xor_sync(0xFFFFFFFFu, s,  off);
        ss += __shfl_xor_sync(0xFFFFFFFFu, ss, off);
    }
    __shared__ float sh_s[8], sh_ss[8];
    const int wid = threadIdx.x >> 5;
    const int lid = threadIdx.x & 31;
    if (lid == 0) { sh_s[wid] = s; sh_ss[wid] = ss; }
    __syncthreads();
    if (wid == 0) {
        s  = (lid < 8) ? sh_s[lid]  : 0.0f;
        ss = (lid < 8) ? sh_ss[lid] : 0.0f;
        #pragma unroll
        for (int off = 4; off > 0; off >>= 1) {
            s  += __shfl_xor_sync(0xFFFFFFFFu, s,  off);
            ss += __shfl_xor_sync(0xFFFFFFFFu, ss, off);
        }
        if (lid == 0) g_partial[b * CHUNKS + blockIdx.x] = make_float2(s, ss);
    }
}

// Pass 2: normalize + affine + mask. grid = (N/4, B), block = 256 threads.
// Each block handles 4 rows; thread t -> row (t/64), float4 column (t%64).
// Fully-invalid blocks: pure zero-store, no stats load, no sync.
__global__ __launch_bounds__(256) void norm_kernel(const float* __restrict__ x,
                                                   const int* __restrict__ lengths,
                                                   const float* __restrict__ weights,
                                                   const float* __restrict__ biases,
                                                   float* __restrict__ out) {
    const int b = blockIdx.y;
    const int len = lengths[b];
    const int base = blockIdx.x * 4;
    const int row = base + (threadIdx.x >> 6);
    const int c = threadIdx.x & 63;  // float4 index within row

    const size_t idx = ((size_t)b * NN + row) * (DD / 4) + c;
    float4* __restrict__ op = reinterpret_cast<float4*>(out);

    if (base >= len) {  // whole block past the valid region
        op[idx] = make_float4(0.0f, 0.0f, 0.0f, 0.0f);
        return;
    }

    // Warp 0 reduces the 16 chunk-partials for this batch; broadcast via smem.
    __shared__ float sh_mean, sh_inv;
    if (threadIdx.x < 32) {
        float s = 0.0f, ss = 0.0f;
        if (threadIdx.x < CHUNKS) {
            float2 p = g_partial[b * CHUNKS + threadIdx.x];
            s = p.x; ss = p.y;
        }
        #pragma unroll
        for (int off = 8; off > 0; off >>= 1) {
            s  += __shfl_xor_sync(0xFFFFFFFFu, s,  off);
            ss += __shfl_xor_sync(0xFFFFFFFFu, ss, off);
        }
        if (threadIdx.x == 0) {
            const float denom = (float)len * (float)DD;
            const float mean  = s / denom;
            const float var   = fmaxf(ss / denom - mean * mean, 0.0f);
            sh_mean = mean;
            sh_inv  = 1.0f / (sqrtf(var) + EPS);
        }
    }
    __syncthreads();

    if (row >= len) {  // partially-valid block, this row invalid
        op[idx] = make_float4(0.0f, 0.0f, 0.0f, 0.0f);
        return;
    }

    const float mean = sh_mean;
    const float inv  = sh_inv;

    const float4 v = reinterpret_cast<const float4*>(x)[idx];
    const float4 w = reinterpret_cast<const float4*>(weights)[c];
    const float4 bi = reinterpret_cast<const float4*>(biases)[c];

    float4 o;
    o.x = (v.x - mean) * inv * w.x + bi.x;
    o.y = (v.y - mean) * inv * w.y + bi.y;
    o.z = (v.z - mean) * inv * w.z + bi.z;
    o.w = (v.w - mean) * inv * w.w + bi.w;
    op[idx] = o;
}

extern "C" void kernel_launch(void* const* d_in, const int* in_sizes, int n_in,
                              void* d_out, int out_size) {
    const float* x        = (const float*)d_in[0];
    const int*   lengths  = (const int*)d_in[1];
    const float* weights  = (const float*)d_in[2];
    const float* biases   = (const float*)d_in[3];
    float* out = (float*)d_out;

    stats_kernel<<<dim3(CHUNKS, BB), 256>>>(x, lengths);
    norm_kernel<<<dim3(NN / 4, BB), 256>>>(x, lengths, weights, biases, out);
}

// round 6
// speedup vs baseline: 1.4340x; 1.4340x over previous
#include <cuda_runtime.h>
#include <cuda_bf16.h>

#define BB 64
#define NN 2048
#define DD 256
#define EPS 1e-05f

#define CHUNKS 16
#define ROWS_PER_CHUNK (NN / CHUNKS)  // 128

// Per-(batch, chunk) partial (sum, sumsq). Owned-slot writes: no zeroing, no atomics.
__device__ float2 g_partial[BB * CHUNKS];
// Per-batch (mean, inv_std) computed by finalize_kernel.
__device__ float2 g_mi[BB];

// Pass 1: per-batch-chunk sum and sum-of-squares over valid rows only.
// grid = (CHUNKS, B), block = 256 threads.
__global__ __launch_bounds__(256) void stats_kernel(const float* __restrict__ x,
                                                    const int* __restrict__ lengths) {
    const int b = blockIdx.y;
    const int len = lengths[b];
    const int row0 = blockIdx.x * ROWS_PER_CHUNK;
    const int row1 = min(row0 + ROWS_PER_CHUNK, len);

    float s = 0.0f, ss = 0.0f;
    if (row1 > row0) {
        const float4* __restrict__ p =
            reinterpret_cast<const float4*>(x + (size_t)b * NN * DD) + (size_t)row0 * (DD / 4);
        const int nvec = (row1 - row0) * (DD / 4);
        for (int i = threadIdx.x; i < nvec; i += 256) {
            float4 v = p[i];
            s  += (v.x + v.y) + (v.z + v.w);
            ss += v.x * v.x + v.y * v.y + v.z * v.z + v.w * v.w;
        }
    }

    #pragma unroll
    for (int off = 16; off > 0; off >>= 1) {
        s  += __shfl_xor_sync(0xFFFFFFFFu, s,  off);
        ss += __shfl_xor_sync(0xFFFFFFFFu, ss, off);
    }
    __shared__ float sh_s[8], sh_ss[8];
    const int wid = threadIdx.x >> 5;
    const int lid = threadIdx.x & 31;
    if (lid == 0) { sh_s[wid] = s; sh_ss[wid] = ss; }
    __syncthreads();
    if (wid == 0) {
        s  = (lid < 8) ? sh_s[lid]  : 0.0f;
        ss = (lid < 8) ? sh_ss[lid] : 0.0f;
        #pragma unroll
        for (int off = 4; off > 0; off >>= 1) {
            s  += __shfl_xor_sync(0xFFFFFFFFu, s,  off);
            ss += __shfl_xor_sync(0xFFFFFFFFu, ss, off);
        }
        if (lid == 0) g_partial[b * CHUNKS + blockIdx.x] = make_float2(s, ss);
    }
}

// Finalize: 1 block, 64 threads. Thread b reduces its 16 partials (unrolled ->
// MLP=16 independent loads) and writes per-batch (mean, inv).
__global__ void finalize_kernel(const int* __restrict__ lengths) {
    const int b = threadIdx.x;
    if (b >= BB) return;
    float s = 0.0f, ss = 0.0f;
    #pragma unroll
    for (int i = 0; i < CHUNKS; i++) {
        float2 p = g_partial[b * CHUNKS + i];
        s += p.x; ss += p.y;
    }
    const float denom = (float)lengths[b] * (float)DD;
    const float mean  = s / denom;
    const float var   = fmaxf(ss / denom - mean * mean, 0.0f);
    g_mi[b] = make_float2(mean, 1.0f / (sqrtf(var) + EPS));
}

// Pass 2: normalize + affine + mask. grid = (NN/16, B), block = 256.
// Block covers 16 rows; thread t -> rows base + (t>>6) + {0,4,8,12}, float4 col t&63.
// No smem, no syncthreads. Streaming stores keep the output out of L2.
__global__ __launch_bounds__(256) void norm_kernel(const float* __restrict__ x,
                                                   const int* __restrict__ lengths,
                                                   const float* __restrict__ weights,
                                                   const float* __restrict__ biases,
                                                   float* __restrict__ out) {
    const int b = blockIdx.y;
    const int len = lengths[b];
    const int base = blockIdx.x * 16;
    const int r = base + (threadIdx.x >> 6);
    const int c = threadIdx.x & 63;

    float4* __restrict__ op = reinterpret_cast<float4*>(out);
    const size_t bidx = (size_t)b * NN * (DD / 4) + c;
    const float4 z = make_float4(0.0f, 0.0f, 0.0f, 0.0f);

    if (base >= len) {  // fully invalid block: pure streaming zero-fill
        #pragma unroll
        for (int k = 0; k < 4; k++)
            __stcs(&op[bidx + (size_t)(r + 4 * k) * (DD / 4)], z);
        return;
    }

    const float2 mi = g_mi[b];
    const float mean = mi.x, inv = mi.y;
    const float4 w  = reinterpret_cast<const float4*>(weights)[c];
    const float4 bi = reinterpret_cast<const float4*>(biases)[c];

    if (base + 16 <= len) {  // fully valid block: no per-row checks
        #pragma unroll
        for (int k = 0; k < 4; k++) {
            const size_t idx = bidx + (size_t)(r + 4 * k) * (DD / 4);
            const float4 v = reinterpret_cast<const float4*>(x)[idx];
            float4 o;
            o.x = (v.x - mean) * inv * w.x + bi.x;
            o.y = (v.y - mean) * inv * w.y + bi.y;
            o.z = (v.z - mean) * inv * w.z + bi.z;
            o.w = (v.w - mean) * inv * w.w + bi.w;
            __stcs(&op[idx], o);
        }
        return;
    }

    // Mixed block: per-row validity.
    #pragma unroll
    for (int k = 0; k < 4; k++) {
        const int row = r + 4 * k;
        const size_t idx = bidx + (size_t)row * (DD / 4);
        if (row < len) {
            const float4 v = reinterpret_cast<const float4*>(x)[idx];
            float4 o;
            o.x = (v.x - mean) * inv * w.x + bi.x;
            o.y = (v.y - mean) * inv * w.y + bi.y;
            o.z = (v.z - mean) * inv * w.z + bi.z;
            o.w = (v.w - mean) * inv * w.w + bi.w;
            __stcs(&op[idx], o);
        } else {
            __stcs(&op[idx], z);
        }
    }
}

extern "C" void kernel_launch(void* const* d_in, const int* in_sizes, int n_in,
                              void* d_out, int out_size) {
    const float* x        = (const float*)d_in[0];
    const int*   lengths  = (const int*)d_in[1];
    const float* weights  = (const float*)d_in[2];
    const float* biases   = (const float*)d_in[3];
    float* out = (float*)d_out;

    stats_kernel<<<dim3(CHUNKS, BB), 256>>>(x, lengths);
    finalize_kernel<<<1, 64>>>(lengths);
    norm_kernel<<<dim3(NN / 16, BB), 256>>>(x, lengths, weights, biases, out);
}

// round 7
// speedup vs baseline: 1.4420x; 1.0056x over previous
#include <cuda_runtime.h>
#include <cuda_bf16.h>

#define BB 64
#define NN 2048
#define DD 256
#define EPS 1e-05f

#define CHUNKS 32
#define ROWS_PER_CHUNK (NN / CHUNKS)  // 64

// Per-(batch, chunk) partial (sum, sumsq). Owned-slot writes: no zeroing, no atomics.
__device__ float2 g_partial[BB * CHUNKS];
// Per-batch (mean, inv_std).
__device__ float2 g_mi[BB];
// Per-batch arrival counter for in-kernel finalize. Starts 0 (static init),
// reset to 0 by the finalize block each launch -> deterministic across replays.
__device__ unsigned int g_count[BB];

// Pass 1 + finalize: grid = (CHUNKS + 1, B), block = 256 threads.
// blockIdx.x < CHUNKS: compute partial (sum, sumsq) over this chunk's valid rows,
//   publish, fence, signal arrival.
// blockIdx.x == CHUNKS: one warp spins until all CHUNKS partials arrived, reduces
//   them, writes (mean, inv), resets the counter.
__global__ __launch_bounds__(256) void stats_kernel(const float* __restrict__ x,
                                                    const int* __restrict__ lengths) {
    const int b = blockIdx.y;

    if (blockIdx.x == CHUNKS) {
        // Finalize block: warp 0 only.
        if (threadIdx.x >= 32) return;
        const int lid = threadIdx.x;
        if (lid == 0) {
            while (atomicAdd(&g_count[b], 0u) < CHUNKS) __nanosleep(64);
        }
        __syncwarp();
        __threadfence();
        float2 p = g_partial[b * CHUNKS + lid];  // 32 lanes <-> 32 chunks
        float s = p.x, ss = p.y;
        #pragma unroll
        for (int off = 16; off > 0; off >>= 1) {
            s  += __shfl_xor_sync(0xFFFFFFFFu, s,  off);
            ss += __shfl_xor_sync(0xFFFFFFFFu, ss, off);
        }
        if (lid == 0) {
            const float denom = (float)lengths[b] * (float)DD;
            const float mean  = s / denom;
            const float var   = fmaxf(ss / denom - mean * mean, 0.0f);
            g_mi[b] = make_float2(mean, 1.0f / (sqrtf(var) + EPS));
            atomicExch(&g_count[b], 0u);  // re-arm for next graph replay
        }
        return;
    }

    const int len = lengths[b];
    const int row0 = blockIdx.x * ROWS_PER_CHUNK;
    const int row1 = min(row0 + ROWS_PER_CHUNK, len);

    // 4 independent accumulator pairs -> 4 float4 loads in flight (MLP=4).
    float s0 = 0.f, s1 = 0.f, s2 = 0.f, s3 = 0.f;
    float q0 = 0.f, q1 = 0.f, q2 = 0.f, q3 = 0.f;
    if (row1 > row0) {
        const float4* __restrict__ p =
            reinterpret_cast<const float4*>(x + (size_t)b * NN * DD) + (size_t)row0 * (DD / 4);
        const int nvec = (row1 - row0) * (DD / 4);
        int i = threadIdx.x;
        for (; i + 768 < nvec; i += 1024) {
            float4 a = p[i];
            float4 v1 = p[i + 256];
            float4 v2 = p[i + 512];
            float4 v3 = p[i + 768];
            s0 += (a.x + a.y) + (a.z + a.w);
            q0 += a.x * a.x + a.y * a.y + a.z * a.z + a.w * a.w;
            s1 += (v1.x + v1.y) + (v1.z + v1.w);
            q1 += v1.x * v1.x + v1.y * v1.y + v1.z * v1.z + v1.w * v1.w;
            s2 += (v2.x + v2.y) + (v2.z + v2.w);
            q2 += v2.x * v2.x + v2.y * v2.y + v2.z * v2.z + v2.w * v2.w;
            s3 += (v3.x + v3.y) + (v3.z + v3.w);
            q3 += v3.x * v3.x + v3.y * v3.y + v3.z * v3.z + v3.w * v3.w;
        }
        for (; i < nvec; i += 256) {
            float4 a = p[i];
            s0 += (a.x + a.y) + (a.z + a.w);
            q0 += a.x * a.x + a.y * a.y + a.z * a.z + a.w * a.w;
        }
    }
    float s  = (s0 + s1) + (s2 + s3);
    float ss = (q0 + q1) + (q2 + q3);

    #pragma unroll
    for (int off = 16; off > 0; off >>= 1) {
        s  += __shfl_xor_sync(0xFFFFFFFFu, s,  off);
        ss += __shfl_xor_sync(0xFFFFFFFFu, ss, off);
    }
    __shared__ float sh_s[8], sh_ss[8];
    const int wid = threadIdx.x >> 5;
    const int lid = threadIdx.x & 31;
    if (lid == 0) { sh_s[wid] = s; sh_ss[wid] = ss; }
    __syncthreads();
    if (wid == 0) {
        s  = (lid < 8) ? sh_s[lid]  : 0.0f;
        ss = (lid < 8) ? sh_ss[lid] : 0.0f;
        #pragma unroll
        for (int off = 4; off > 0; off >>= 1) {
            s  += __shfl_xor_sync(0xFFFFFFFFu, s,  off);
            ss += __shfl_xor_sync(0xFFFFFFFFu, ss, off);
        }
        if (lid == 0) {
            g_partial[b * CHUNKS + blockIdx.x] = make_float2(s, ss);
            __threadfence();
            atomicAdd(&g_count[b], 1u);  // signal arrival
        }
    }
}

// Pass 2: normalize + affine + mask. grid = (NN/16, B), block = 256.
// Block covers 16 rows; thread t -> rows base + (t>>6) + {0,4,8,12}, float4 col t&63.
// No smem, no syncthreads. Streaming stores keep the output out of L2.
__global__ __launch_bounds__(256) void norm_kernel(const float* __restrict__ x,
                                                   const int* __restrict__ lengths,
                                                   const float* __restrict__ weights,
                                                   const float* __restrict__ biases,
                                                   float* __restrict__ out) {
    const int b = blockIdx.y;
    const int len = lengths[b];
    const int base = blockIdx.x * 16;
    const int r = base + (threadIdx.x >> 6);
    const int c = threadIdx.x & 63;

    float4* __restrict__ op = reinterpret_cast<float4*>(out);
    const size_t bidx = (size_t)b * NN * (DD / 4) + c;
    const float4 z = make_float4(0.0f, 0.0f, 0.0f, 0.0f);

    if (base >= len) {  // fully invalid block: pure streaming zero-fill
        #pragma unroll
        for (int k = 0; k < 4; k++)
            __stcs(&op[bidx + (size_t)(r + 4 * k) * (DD / 4)], z);
        return;
    }

    const float2 mi = g_mi[b];
    const float mean = mi.x, inv = mi.y;
    const float4 w  = reinterpret_cast<const float4*>(weights)[c];
    const float4 bi = reinterpret_cast<const float4*>(biases)[c];

    if (base + 16 <= len) {  // fully valid block: no per-row checks
        #pragma unroll
        for (int k = 0; k < 4; k++) {
            const size_t idx = bidx + (size_t)(r + 4 * k) * (DD / 4);
            const float4 v = reinterpret_cast<const float4*>(x)[idx];
            float4 o;
            o.x = (v.x - mean) * inv * w.x + bi.x;
            o.y = (v.y - mean) * inv * w.y + bi.y;
            o.z = (v.z - mean) * inv * w.z + bi.z;
            o.w = (v.w - mean) * inv * w.w + bi.w;
            __stcs(&op[idx], o);
        }
        return;
    }

    // Mixed block: per-row validity.
    #pragma unroll
    for (int k = 0; k < 4; k++) {
        const int row = r + 4 * k;
        const size_t idx = bidx + (size_t)row * (DD / 4);
        if (row < len) {
            const float4 v = reinterpret_cast<const float4*>(x)[idx];
            float4 o;
            o.x = (v.x - mean) * inv * w.x + bi.x;
            o.y = (v.y - mean) * inv * w.y + bi.y;
            o.z = (v.z - mean) * inv * w.z + bi.z;
            o.w = (v.w - mean) * inv * w.w + bi.w;
            __stcs(&op[idx], o);
        } else {
            __stcs(&op[idx], z);
        }
    }
}

extern "C" void kernel_launch(void* const* d_in, const int* in_sizes, int n_in,
                              void* d_out, int out_size) {
    const float* x        = (const float*)d_in[0];
    const int*   lengths  = (const int*)d_in[1];
    const float* weights  = (const float*)d_in[2];
    const float* biases   = (const float*)d_in[3];
    float* out = (float*)d_out;

    stats_kernel<<<dim3(CHUNKS + 1, BB), 256>>>(x, lengths);
    norm_kernel<<<dim3(NN / 16, BB), 256>>>(x, lengths, weights, biases, out);
}

// round 8
// speedup vs baseline: 1.5099x; 1.0471x over previous
#include <cuda_runtime.h>
#include <cuda_bf16.h>

#define BB 64
#define NN 2048
#define DD 256
#define EPS 1e-05f

#define CHUNKS 32
#define ROWS_PER_CHUNK (NN / CHUNKS)   // 64
#define ROWS_PER_NORM 16
#define NPARTS (NN / ROWS_PER_NORM)    // 128 norm blocks per batch
#define STATS_BLOCKS (BB * CHUNKS)     // 2048
#define FLAG_DONE (CHUNKS + 1)         // 33

// Owned-slot partials: no zeroing, no data races.
__device__ float2 g_partial[BB * CHUNKS];
__device__ float2 g_mi[BB];
// Protocol counters. Static-init 0; each launch restores them to 0 -> graph-safe.
__device__ unsigned int g_count[BB];
__device__ unsigned int g_done[BB];

__global__ __launch_bounds__(256) void fused_kernel(const float* __restrict__ x,
                                                    const int* __restrict__ lengths,
                                                    const float* __restrict__ weights,
                                                    const float* __restrict__ biases,
                                                    float* __restrict__ out) {
    const int bid = blockIdx.x;

    if (bid < STATS_BLOCKS) {
        // ---------------- Stats phase ----------------
        const int b = bid >> 5;       // batch
        const int chunk = bid & 31;
        const int len = lengths[b];
        const int row0 = chunk * ROWS_PER_CHUNK;
        const int row1 = min(row0 + ROWS_PER_CHUNK, len);

        float s0 = 0.f, s1 = 0.f, s2 = 0.f, s3 = 0.f;
        float q0 = 0.f, q1 = 0.f, q2 = 0.f, q3 = 0.f;
        if (row1 > row0) {
            const float4* __restrict__ p =
                reinterpret_cast<const float4*>(x + (size_t)b * NN * DD) + (size_t)row0 * (DD / 4);
            const int nvec = (row1 - row0) * (DD / 4);
            int i = threadIdx.x;
            for (; i + 768 < nvec; i += 1024) {
                float4 a  = p[i];
                float4 v1 = p[i + 256];
                float4 v2 = p[i + 512];
                float4 v3 = p[i + 768];
                s0 += (a.x + a.y) + (a.z + a.w);
                q0 += a.x * a.x + a.y * a.y + a.z * a.z + a.w * a.w;
                s1 += (v1.x + v1.y) + (v1.z + v1.w);
                q1 += v1.x * v1.x + v1.y * v1.y + v1.z * v1.z + v1.w * v1.w;
                s2 += (v2.x + v2.y) + (v2.z + v2.w);
                q2 += v2.x * v2.x + v2.y * v2.y + v2.z * v2.z + v2.w * v2.w;
                s3 += (v3.x + v3.y) + (v3.z + v3.w);
                q3 += v3.x * v3.x + v3.y * v3.y + v3.z * v3.z + v3.w * v3.w;
            }
            for (; i < nvec; i += 256) {
                float4 a = p[i];
                s0 += (a.x + a.y) + (a.z + a.w);
                q0 += a.x * a.x + a.y * a.y + a.z * a.z + a.w * a.w;
            }
        }
        float s  = (s0 + s1) + (s2 + s3);
        float ss = (q0 + q1) + (q2 + q3);

        #pragma unroll
        for (int off = 16; off > 0; off >>= 1) {
            s  += __shfl_xor_sync(0xFFFFFFFFu, s,  off);
            ss += __shfl_xor_sync(0xFFFFFFFFu, ss, off);
        }
        __shared__ float sh_s[8], sh_ss[8];
        const int wid = threadIdx.x >> 5;
        const int lid = threadIdx.x & 31;
        if (lid == 0) { sh_s[wid] = s; sh_ss[wid] = ss; }
        __syncthreads();
        if (wid != 0) return;
        s  = (lid < 8) ? sh_s[lid]  : 0.0f;
        ss = (lid < 8) ? sh_ss[lid] : 0.0f;
        #pragma unroll
        for (int off = 4; off > 0; off >>= 1) {
            s  += __shfl_xor_sync(0xFFFFFFFFu, s,  off);
            ss += __shfl_xor_sync(0xFFFFFFFFu, ss, off);
        }
        if (lid != 0) return;

        g_partial[b * CHUNKS + chunk] = make_float2(s, ss);
        __threadfence();
        const unsigned int old = atomicAdd(&g_count[b], 1u);
        if (old == CHUNKS - 1) {
            // Last arrival for this batch: finalize (all partials published+fenced).
            __threadfence();
            float fs = 0.0f, fss = 0.0f;
            #pragma unroll
            for (int i = 0; i < CHUNKS; i++) {
                float2 p = __ldcg(&g_partial[b * CHUNKS + i]);
                fs += p.x; fss += p.y;
            }
            const float denom = (float)len * (float)DD;
            const float mean  = fs / denom;
            const float var   = fmaxf(fss / denom - mean * mean, 0.0f);
            g_mi[b] = make_float2(mean, 1.0f / (sqrtf(var) + EPS));
            __threadfence();
            atomicExch(&g_count[b], FLAG_DONE);  // release flag
        }
        return;
    }

    // ---------------- Norm phase ----------------
    const int nb = bid - STATS_BLOCKS;
    const int b = nb >> 7;        // batch (batch-major: pipeline with stats)
    const int part = nb & (NPARTS - 1);
    const int len = lengths[b];
    const int base = part * ROWS_PER_NORM;
    const int r = base + (threadIdx.x >> 6);
    const int c = threadIdx.x & 63;

    float4* __restrict__ op = reinterpret_cast<float4*>(out);
    const size_t bidx = (size_t)b * NN * (DD / 4) + c;
    const float4 z = make_float4(0.0f, 0.0f, 0.0f, 0.0f);

    if (base >= len) {  // fully invalid: no stats needed, pure streaming zero-fill
        #pragma unroll
        for (int k = 0; k < 4; k++)
            __stcs(&op[bidx + (size_t)(r + 4 * k) * (DD / 4)], z);
        if (threadIdx.x == 0) {
            const unsigned int d = atomicAdd(&g_done[b], 1u);
            if (d == NPARTS - 1) {            // last norm block: re-arm protocol
                atomicExch(&g_count[b], 0u);
                atomicExch(&g_done[b], 0u);
            }
        }
        return;
    }

    // Gate on this batch's stats.
    if (threadIdx.x == 0) {
        while (*(volatile unsigned int*)&g_count[b] != FLAG_DONE) __nanosleep(32);
        __threadfence();
    }
    __syncthreads();

    const float2 mi = __ldcg(&g_mi[b]);   // L2 read: avoid stale L1 line
    const float mean = mi.x, inv = mi.y;
    const float4 w  = reinterpret_cast<const float4*>(weights)[c];
    const float4 bi = reinterpret_cast<const float4*>(biases)[c];

    if (base + ROWS_PER_NORM <= len) {  // fully valid: no per-row checks
        #pragma unroll
        for (int k = 0; k < 4; k++) {
            const size_t idx = bidx + (size_t)(r + 4 * k) * (DD / 4);
            const float4 v = reinterpret_cast<const float4*>(x)[idx];
            float4 o;
            o.x = (v.x - mean) * inv * w.x + bi.x;
            o.y = (v.y - mean) * inv * w.y + bi.y;
            o.z = (v.z - mean) * inv * w.z + bi.z;
            o.w = (v.w - mean) * inv * w.w + bi.w;
            __stcs(&op[idx], o);
        }
    } else {
        // Mixed block: per-row validity.
        #pragma unroll
        for (int k = 0; k < 4; k++) {
            const int row = r + 4 * k;
            const size_t idx = bidx + (size_t)row * (DD / 4);
            if (row < len) {
                const float4 v = reinterpret_cast<const float4*>(x)[idx];
                float4 o;
                o.x = (v.x - mean) * inv * w.x + bi.x;
                o.y = (v.y - mean) * inv * w.y + bi.y;
                o.z = (v.z - mean) * inv * w.z + bi.z;
                o.w = (v.w - mean) * inv * w.w + bi.w;
                __stcs(&op[idx], o);
            } else {
                __stcs(&op[idx], z);
            }
        }
    }

    if (threadIdx.x == 0) {
        const unsigned int d = atomicAdd(&g_done[b], 1u);
        if (d == NPARTS - 1) {                // last norm block: re-arm protocol
            atomicExch(&g_count[b], 0u);
            atomicExch(&g_done[b], 0u);
        }
    }
}

extern "C" void kernel_launch(void* const* d_in, const int* in_sizes, int n_in,
                              void* d_out, int out_size) {
    const float* x        = (const float*)d_in[0];
    const int*   lengths  = (const int*)d_in[1];
    const float* weights  = (const float*)d_in[2];
    const float* biases   = (const float*)d_in[3];
    float* out = (float*)d_out;

    fused_kernel<<<STATS_BLOCKS + BB * NPARTS, 256>>>(x, lengths, weights, biases, out);
}